// round 11
// baseline (speedup 1.0000x reference)
#include <cuda_runtime.h>
#include <cuda_fp16.h>
#include <cstdint>

// SinkhornDistance: B=64, N=M=1024, eps=0.1, 50 iterations.
// Scaling domain: K = exp(-C/eps); a = (mu+1e-8)/(K b); b = (nu+1e-8)/(K^T a)
// pi = exp(-C/eps) * a_i * b_j (fp32) ; cost_b = sum pi*C.  b0 = 1 (scale-inv).
//
// R11 = R10 (persistent, smem-resident K, dataflow flags) with phase 1's
// row-dot + reduce moved to the tensor pipe: mma.sync.m16n8k16 (fp16 in,
// fp32 accum) on the row-major smem ktile via ldmatrix.x4, b replicated
// across the 8 MMA columns from an smem fp16 stage. Kills the 31-shfl
// folded reduce and ~100 FMA-pipe instrs per thread-epoch.

#define BATCH 64
#define NN 1024
#define INV_EPS 10.0f
#define LOGEPS 1e-8f
#define MAX_ITER 50
#define ASCALE 4096.0f       // 2^12, exact; cancels in b = nu*ASCALE/T_scaled

#define RPB 16               // rows per block
#define BPB 64               // blocks per team (= NN/RPB)

// Scratch (static device globals; no runtime allocation)
__device__ float g_T[3][BATCH * NN];     // rotation buffers (scaled col sums)
__device__ unsigned g_cnt[BATCH];        // arrival counters (monotonic)
__device__ unsigned g_flag[BATCH];       // completed-epoch flag (monotonic)

__device__ __forceinline__ unsigned ld_acq(const unsigned* p) {
    unsigned v;
    asm volatile("ld.acquire.gpu.b32 %0, [%1];" : "=r"(v) : "l"(p) : "memory");
    return v;
}
__device__ __forceinline__ void st_rel(unsigned* p, unsigned v) {
    asm volatile("st.release.gpu.b32 [%0], %1;" :: "l"(p), "r"(v) : "memory");
}
__device__ __forceinline__ uint32_t smem_u32(const void* p) {
    return (uint32_t)__cvta_generic_to_shared(p);
}
__device__ __forceinline__ void ldsm_x4(uint32_t& r0, uint32_t& r1,
                                        uint32_t& r2, uint32_t& r3,
                                        uint32_t addr) {
    asm volatile("ldmatrix.sync.aligned.m8n8.x4.shared.b16 {%0,%1,%2,%3}, [%4];"
                 : "=r"(r0), "=r"(r1), "=r"(r2), "=r"(r3) : "r"(addr));
}
__device__ __forceinline__ void mma16816(float& d0, float& d1, float& d2, float& d3,
                                         uint32_t a0, uint32_t a1, uint32_t a2,
                                         uint32_t a3, uint32_t b0, uint32_t b1) {
    asm volatile(
        "mma.sync.aligned.m16n8k16.row.col.f32.f16.f16.f32 "
        "{%0,%1,%2,%3},{%4,%5,%6,%7},{%8,%9},{%0,%1,%2,%3};"
        : "+f"(d0), "+f"(d1), "+f"(d2), "+f"(d3)
        : "r"(a0), "r"(a1), "r"(a2), "r"(a3), "r"(b0), "r"(b1));
}

// ---------------------------------------------------------------------------
// Zero T[0] (all batches), cost, counters, flags. grid = 64 x 256.
__global__ void k_init(float* __restrict__ cost) {
    int idx = blockIdx.x * 256 + threadIdx.x;  // 16384 float4 = 64K floats
    ((float4*)g_T[0])[idx] = make_float4(0.f, 0.f, 0.f, 0.f);
    if (blockIdx.x == 0 && threadIdx.x < BATCH) {
        cost[threadIdx.x] = 0.0f;
        g_cnt[threadIdx.x] = 0u;
        g_flag[threadIdx.x] = 0u;
    }
}

// ---------------------------------------------------------------------------
__global__ void __launch_bounds__(256, 6) sinkhorn_resident(
    const float* __restrict__ mu, const float* __restrict__ nu,
    const float* __restrict__ C, float* __restrict__ cost,
    float* __restrict__ pi, int teams)
{
    const int team = blockIdx.x >> 6;    // /BPB
    const int blk  = blockIdx.x & 63;
    const int r0   = blk * RPB;
    const int tid  = threadIdx.x;
    const int lane = tid & 31, warp = tid >> 5;

    __shared__ uint2 ktile[RPB][256];    // 32 KB fp16 K tile (row-major rows)
    __shared__ uint32_t bsh[NN / 2];     // 2 KB: b as fp16 pairs
    __shared__ float mush[RPB];
    __shared__ float atrue[RPB];         // true a (epilogue)
    __shared__ uint32_t ash2[RPB];       // half2(a*ASCALE) broadcast pairs
    __shared__ float wsum[RPB][9];       // padded

    // ldmatrix lane address into ktile (A-fragment idiom for m16k16 tiles):
    // lanes 0-15 -> rows 0-15 (first 16B of chunk), lanes 16-31 -> rows + 16B.
    const uint32_t kbase = smem_u32(&ktile[0][0]);
    const uint32_t lm_base =
        kbase + (uint32_t)(lane & 15) * 2048u + ((lane >> 4) & 1) * 16u
              + (uint32_t)warp * 256u;  // warp covers cols [warp*128, +128)
    const uint32_t bbase = smem_u32(bsh);
    const uint32_t b_off0 = (uint32_t)(warp * 128 + 2 * (lane & 3)) * 2u;

    for (int batch = team; batch < BATCH; batch += teams) {
        // ---- round setup: mu, nu, and the smem-resident K tile from C ----
        if (tid < RPB) mush[tid] = mu[(size_t)batch * NN + r0 + tid] + LOGEPS;
        float4 nv = ((const float4*)(nu + (size_t)batch * NN))[tid];
        nv.x = (nv.x + LOGEPS) * ASCALE;
        nv.y = (nv.y + LOGEPS) * ASCALE;
        nv.z = (nv.z + LOGEPS) * ASCALE;
        nv.w = (nv.w + LOGEPS) * ASCALE;

#pragma unroll
        for (int r = 0; r < RPB; r++) {
            float4 c = ((const float4*)(C + ((size_t)batch * NN + r0 + r) * NN))[tid];
            __half2 h0 = __floats2half2_rn(__expf(-c.x * INV_EPS),
                                           __expf(-c.y * INV_EPS));
            __half2 h1 = __floats2half2_rn(__expf(-c.z * INV_EPS),
                                           __expf(-c.w * INV_EPS));
            uint2 pk;
            pk.x = *(const unsigned*)&h0;
            pk.y = *(const unsigned*)&h1;
            ktile[r][tid] = pk;
        }

        unsigned* cntp  = &g_cnt[batch];
        unsigned* flagp = &g_flag[batch];

        // ---- 50 iterations, dataflow-synced across the 64-block team ----
        for (int it = 0; it < MAX_ITER; it++) {
            if (it > 0) {
                if (tid == 0) {
                    while (ld_acq(flagp) < (unsigned)it) { }
                }
                __syncthreads();
            }

            // b at this thread's 4 columns -> stage to smem as fp16 pairs.
            __half2 bh01, bh23;
            if (it == 0) {
                bh01 = __floats2half2_rn(1.f, 1.f);
                bh23 = bh01;
            } else {
                float4 t = ((const float4*)&g_T[(it + 2) % 3][(size_t)batch * NN])[tid];
                bh01 = __floats2half2_rn(__fdividef(nv.x, t.x),
                                         __fdividef(nv.y, t.y));
                bh23 = __floats2half2_rn(__fdividef(nv.z, t.z),
                                         __fdividef(nv.w, t.w));
            }
            bsh[tid * 2]     = *(const uint32_t*)&bh01;  // cols 4t,4t+1
            bsh[tid * 2 + 1] = *(const uint32_t*)&bh23;  // cols 4t+2,4t+3

            // Zero-ahead: T[(it+1)%3] has no remaining readers. Race-free.
            if (blk == 0)
                ((float4*)&g_T[(it + 1) % 3][(size_t)batch * NN])[tid] =
                    make_float4(0.f, 0.f, 0.f, 0.f);

            __syncthreads();   // bsh visible to all warps

            // Phase 1 (tensor pipe): s = K_tile(16x1024) . b via 8 chunked
            // m16n8k16 MMAs per warp; b replicated across the 8 N-columns.
            float d0 = 0.f, d1 = 0.f, d2 = 0.f, d3 = 0.f;
#pragma unroll
            for (int j = 0; j < 8; j++) {
                uint32_t a0, a1, a2, a3;
                ldsm_x4(a0, a1, a2, a3, lm_base + (uint32_t)j * 32u);
                uint32_t b0 = *(const uint32_t*)((const char*)bsh + b_off0 + j * 32);
                uint32_t b1 = *(const uint32_t*)((const char*)bsh + b_off0 + j * 32 + 16);
                mma16816(d0, d1, d2, d3, a0, a1, a2, a3, b0, b1);
            }
            // D col 0 = row sums: lanes l%4==0 hold rows l/4 (d0), l/4+8 (d2).
            if ((lane & 3) == 0) {
                wsum[lane >> 2][warp] = d0;
                wsum[(lane >> 2) + 8][warp] = d2;
            }
            __syncthreads();

            // Cross-warp combine + divide (tiny, smem-only).
            if (tid < RPB) {
                float s = 0.f;
#pragma unroll
                for (int w = 0; w < 8; w++) s += wsum[tid][w];
                float a = __fdividef(mush[tid], s);
                atrue[tid] = a;
                __half2 ah = __float2half2_rn(a * ASCALE);
                ash2[tid] = *(const uint32_t*)&ah;
            }
            __syncthreads();

            // Phase 2: scaled half2 column partials from the smem tile.
            __half2 acc01 = __floats2half2_rn(0.f, 0.f);
            __half2 acc23 = acc01;
#pragma unroll
            for (int r = 0; r < RPB; r++) {
                uint32_t ahu = ash2[r];
                __half2 ah = *(const __half2*)&ahu;
                uint2 kv = ktile[r][tid];
                acc01 = __hfma2(*(__half2*)&kv.x, ah, acc01);
                acc23 = __hfma2(*(__half2*)&kv.y, ah, acc23);
            }
            float2 a01 = __half22float2(acc01);
            float2 a23 = __half22float2(acc23);
            atomicAdd((float4*)(&g_T[it % 3][(size_t)batch * NN] + tid * 4),
                      make_float4(a01.x, a01.y, a23.x, a23.y));

            // Arrive: fence -> count -> release flag (same protocol as R10).
            __syncthreads();
            if (tid == 0) {
                __threadfence();
                unsigned old = atomicAdd(cntp, 1u);
                if ((old & 63u) == 63u) st_rel(flagp, (unsigned)(it + 1));
            }
        }

        // ---- epilogue for this batch (needs all final T contributions) ----
        if (tid == 0) {
            while (ld_acq(flagp) < (unsigned)MAX_ITER) { }
        }
        __syncthreads();

        float4 t = ((const float4*)&g_T[(MAX_ITER - 1) % 3][(size_t)batch * NN])[tid];
        float4 bv;
        bv.x = nv.x / t.x;
        bv.y = nv.y / t.y;
        bv.z = nv.z / t.z;
        bv.w = nv.w / t.w;

        float cacc = 0.0f;
#pragma unroll
        for (int r = 0; r < RPB; r++) {
            float a = atrue[r];
            float4 cv = ((const float4*)(C + ((size_t)batch * NN + r0 + r) * NN))[tid];
            float4 p;
            p.x = __expf(-cv.x * INV_EPS) * a * bv.x;
            p.y = __expf(-cv.y * INV_EPS) * a * bv.y;
            p.z = __expf(-cv.z * INV_EPS) * a * bv.z;
            p.w = __expf(-cv.w * INV_EPS) * a * bv.w;
            cacc += p.x * cv.x + p.y * cv.y + p.z * cv.z + p.w * cv.w;
            ((float4*)(pi + ((size_t)batch * NN + r0 + r) * NN))[tid] = p;
        }
#pragma unroll
        for (int o = 16; o; o >>= 1)
            cacc += __shfl_xor_sync(0xffffffffu, cacc, o);
        if (lane == 0) wsum[warp][0] = cacc;
        __syncthreads();
        if (tid == 0) {
            float s = 0.f;
#pragma unroll
            for (int w = 0; w < 8; w++) s += wsum[w][0];
            atomicAdd(&cost[batch], s);
        }
        __syncthreads();   // protect smem reuse in the next round
    }
}

// ---------------------------------------------------------------------------
extern "C" void kernel_launch(void* const* d_in, const int* in_sizes, int n_in,
                              void* d_out, int out_size) {
    const float* mu = (const float*)d_in[0];
    const float* nu = (const float*)d_in[1];
    const float* C  = (const float*)d_in[2];
    float* cost = (float*)d_out;                 // outputs: (cost[64], pi[64M])
    float* pi   = (float*)d_out + BATCH;

    // Co-residency-safe grid size (pure queries; deterministic per machine).
    int occ = 0, sms = 0, dev = 0;
    cudaGetDevice(&dev);
    cudaOccupancyMaxActiveBlocksPerMultiprocessor(&occ, sinkhorn_resident, 256, 0);
    cudaDeviceGetAttribute(&sms, cudaDevAttrMultiProcessorCount, dev);
    int teams = (occ * sms) / BPB;
    if (teams > BATCH) teams = BATCH;
    if (teams < 1) teams = 1;

    k_init<<<64, 256>>>(cost);
    sinkhorn_resident<<<teams * BPB, 256>>>(mu, nu, C, cost, pi, teams);
}

// round 12
// speedup vs baseline: 2.0975x; 2.0975x over previous
#include <cuda_runtime.h>
#include <cuda_fp16.h>
#include <cstdint>

// SinkhornDistance: B=64, N=M=1024, eps=0.1, 50 iterations.
// Scaling domain: K = exp(-C/eps); a = (mu+1e-8)/(K b); b = (nu+1e-8)/(K^T a)
// pi = exp(-C/eps) * a_i * b_j (fp32) ; cost_b = sum pi*C.  b0 = 1 (scale-inv).
//
// R12 = R10 (persistent, smem-resident K, dataflow sync) + instruction diet:
//  - paired-row tile (uint4 = 2 rows x 4 cols fp16): 8 LDS.128 per phase
//    instead of 16 LDS.64 (conflict-free)
//  - ash2 precomputed as packed half2 (no cvt in phase 2)
//  - spin directly on the arrival counter (flag store removed: one fewer
//    L2 round-trip per epoch)

#define BATCH 64
#define NN 1024
#define INV_EPS 10.0f
#define LOGEPS 1e-8f
#define MAX_ITER 50
#define ASCALE 4096.0f       // 2^12, exact; cancels in b = nu*ASCALE/T_scaled

#define RPB 16               // rows per block
#define BPB 64               // blocks per team (= NN/RPB)

// Scratch (static device globals; no runtime allocation)
__device__ float g_T[3][BATCH * NN];     // rotation buffers (scaled col sums)
__device__ unsigned g_cnt[BATCH];        // arrival counters (monotonic)

__device__ __forceinline__ unsigned ld_acq(const unsigned* p) {
    unsigned v;
    asm volatile("ld.acquire.gpu.b32 %0, [%1];" : "=r"(v) : "l"(p) : "memory");
    return v;
}

// ---------------------------------------------------------------------------
// Zero T[0] (all batches), cost, counters. grid = 64 x 256.
__global__ void k_init(float* __restrict__ cost) {
    int idx = blockIdx.x * 256 + threadIdx.x;  // 16384 float4 = 64K floats
    ((float4*)g_T[0])[idx] = make_float4(0.f, 0.f, 0.f, 0.f);
    if (blockIdx.x == 0 && threadIdx.x < BATCH) {
        cost[threadIdx.x] = 0.0f;
        g_cnt[threadIdx.x] = 0u;
    }
}

// ---------------------------------------------------------------------------
__global__ void __launch_bounds__(256, 6) sinkhorn_resident(
    const float* __restrict__ mu, const float* __restrict__ nu,
    const float* __restrict__ C, float* __restrict__ cost,
    float* __restrict__ pi, int teams)
{
    const int team = blockIdx.x >> 6;    // /BPB
    const int blk  = blockIdx.x & 63;
    const int r0   = blk * RPB;
    const int tid  = threadIdx.x;
    const int lane = tid & 31, warp = tid >> 5;

    // Paired-row K tile: ktile2[r2][tid] = {row 2r2 (2x half2), row 2r2+1}.
    __shared__ uint4 ktile2[RPB / 2][256];   // 32 KB
    __shared__ float mush[RPB];
    __shared__ float atrue[RPB];             // true a (epilogue)
    __shared__ uint32_t ash2[RPB];           // packed half2(a*ASCALE)
    __shared__ float wsum[RPB][9];           // padded

    for (int batch = team; batch < BATCH; batch += teams) {
        // ---- round setup: mu, nu, and the smem-resident K tile from C ----
        if (tid < RPB) mush[tid] = mu[(size_t)batch * NN + r0 + tid] + LOGEPS;
        float4 nv = ((const float4*)(nu + (size_t)batch * NN))[tid];
        nv.x = (nv.x + LOGEPS) * ASCALE;
        nv.y = (nv.y + LOGEPS) * ASCALE;
        nv.z = (nv.z + LOGEPS) * ASCALE;
        nv.w = (nv.w + LOGEPS) * ASCALE;

#pragma unroll
        for (int r2 = 0; r2 < RPB / 2; r2++) {
            float4 c0 = ((const float4*)(C + ((size_t)batch * NN + r0 + 2 * r2) * NN))[tid];
            float4 c1 = ((const float4*)(C + ((size_t)batch * NN + r0 + 2 * r2 + 1) * NN))[tid];
            __half2 h00 = __floats2half2_rn(__expf(-c0.x * INV_EPS),
                                            __expf(-c0.y * INV_EPS));
            __half2 h01 = __floats2half2_rn(__expf(-c0.z * INV_EPS),
                                            __expf(-c0.w * INV_EPS));
            __half2 h10 = __floats2half2_rn(__expf(-c1.x * INV_EPS),
                                            __expf(-c1.y * INV_EPS));
            __half2 h11 = __floats2half2_rn(__expf(-c1.z * INV_EPS),
                                            __expf(-c1.w * INV_EPS));
            uint4 pk;
            pk.x = *(const unsigned*)&h00;
            pk.y = *(const unsigned*)&h01;
            pk.z = *(const unsigned*)&h10;
            pk.w = *(const unsigned*)&h11;
            ktile2[r2][tid] = pk;
        }

        unsigned* cntp = &g_cnt[batch];

        // ---- 50 iterations, dataflow-synced across the 64-block team ----
        for (int it = 0; it < MAX_ITER; it++) {
            if (it > 0) {
                unsigned target = (unsigned)(64 * it);
                if (tid == 0) {
                    while (ld_acq(cntp) < target) { }
                }
                __syncthreads();
            }

            // b at this thread's 4 columns (half2 for the phase-1 dot).
            __half2 bh01, bh23;
            if (it == 0) {
                bh01 = __floats2half2_rn(1.f, 1.f);
                bh23 = bh01;
            } else {
                float4 t = ((const float4*)&g_T[(it + 2) % 3][(size_t)batch * NN])[tid];
                bh01 = __floats2half2_rn(__fdividef(nv.x, t.x),
                                         __fdividef(nv.y, t.y));
                bh23 = __floats2half2_rn(__fdividef(nv.z, t.z),
                                         __fdividef(nv.w, t.w));
            }

            // Zero-ahead: T[(it+1)%3] has no remaining readers. Race-free.
            if (blk == 0)
                ((float4*)&g_T[(it + 1) % 3][(size_t)batch * NN])[tid] =
                    make_float4(0.f, 0.f, 0.f, 0.f);

            // Phase 1: row dots from the paired smem tile (8 LDS.128).
            float part[RPB];
#pragma unroll
            for (int r2 = 0; r2 < RPB / 2; r2++) {
                uint4 kv = ktile2[r2][tid];
                __half2 p0 = __hfma2(*(__half2*)&kv.y, bh23,
                                     __hmul2(*(__half2*)&kv.x, bh01));
                __half2 p1 = __hfma2(*(__half2*)&kv.w, bh23,
                                     __hmul2(*(__half2*)&kv.z, bh01));
                float2 f0 = __half22float2(p0);
                float2 f1 = __half22float2(p1);
                part[2 * r2]     = f0.x + f0.y;
                part[2 * r2 + 1] = f1.x + f1.y;
            }

            // Folded multi-row warp reduce: 31 shfl for 16 rows.
#pragma unroll
            for (int r = 0; r < RPB; r++)
                part[r] += __shfl_xor_sync(0xffffffffu, part[r], 16);
            float u8[8];
#pragma unroll
            for (int j = 0; j < 8; j++) {
                u8[j] = (lane & 16) ? part[j + 8] : part[j];
                u8[j] += __shfl_xor_sync(0xffffffffu, u8[j], 8);
            }
            float u4[4];
#pragma unroll
            for (int j = 0; j < 4; j++) {
                u4[j] = (lane & 8) ? u8[j + 4] : u8[j];
                u4[j] += __shfl_xor_sync(0xffffffffu, u4[j], 4);
            }
            float u2[2];
#pragma unroll
            for (int j = 0; j < 2; j++) {
                u2[j] = (lane & 4) ? u4[j + 2] : u4[j];
                u2[j] += __shfl_xor_sync(0xffffffffu, u2[j], 2);
            }
            float q = (lane & 2) ? u2[1] : u2[0];
            q += __shfl_xor_sync(0xffffffffu, q, 1);
            int R = (lane >> 1) & 15;
            if (!(lane & 1)) wsum[R][warp] = q;
            __syncthreads();

            // Tiny critical section: smem-only + fast divide.
            if (tid < RPB) {
                float s = 0.f;
#pragma unroll
                for (int w = 0; w < 8; w++) s += wsum[tid][w];
                float a = __fdividef(mush[tid], s);
                atrue[tid] = a;
                __half2 ah = __float2half2_rn(a * ASCALE);
                ash2[tid] = *(const uint32_t*)&ah;
            }
            __syncthreads();

            // Phase 2: scaled half2 column partials (8 LDS.128, no cvt).
            __half2 acc01 = __floats2half2_rn(0.f, 0.f);
            __half2 acc23 = acc01;
#pragma unroll
            for (int r2 = 0; r2 < RPB / 2; r2++) {
                uint4 kv = ktile2[r2][tid];
                uint32_t a0u = ash2[2 * r2], a1u = ash2[2 * r2 + 1];
                __half2 a0 = *(const __half2*)&a0u;
                __half2 a1 = *(const __half2*)&a1u;
                acc01 = __hfma2(*(__half2*)&kv.x, a0, acc01);
                acc23 = __hfma2(*(__half2*)&kv.y, a0, acc23);
                acc01 = __hfma2(*(__half2*)&kv.z, a1, acc01);
                acc23 = __hfma2(*(__half2*)&kv.w, a1, acc23);
            }
            float2 a01 = __half22float2(acc01);
            float2 a23 = __half22float2(acc23);
            atomicAdd((float4*)(&g_T[it % 3][(size_t)batch * NN] + tid * 4),
                      make_float4(a01.x, a01.y, a23.x, a23.y));

            // Arrive: fence -> monotonic counter (spinners poll the counter).
            __syncthreads();
            if (tid == 0) {
                __threadfence();
                atomicAdd(cntp, 1u);
            }
        }

        // ---- epilogue for this batch (needs all final T contributions) ----
        if (tid == 0) {
            while (ld_acq(cntp) < (unsigned)(64 * MAX_ITER)) { }
        }
        __syncthreads();

        float4 t = ((const float4*)&g_T[(MAX_ITER - 1) % 3][(size_t)batch * NN])[tid];
        float4 bv;
        bv.x = nv.x / t.x;
        bv.y = nv.y / t.y;
        bv.z = nv.z / t.z;
        bv.w = nv.w / t.w;

        float cacc = 0.0f;
#pragma unroll
        for (int r = 0; r < RPB; r++) {
            float a = atrue[r];
            float4 cv = ((const float4*)(C + ((size_t)batch * NN + r0 + r) * NN))[tid];
            float4 p;
            p.x = __expf(-cv.x * INV_EPS) * a * bv.x;
            p.y = __expf(-cv.y * INV_EPS) * a * bv.y;
            p.z = __expf(-cv.z * INV_EPS) * a * bv.z;
            p.w = __expf(-cv.w * INV_EPS) * a * bv.w;
            cacc += p.x * cv.x + p.y * cv.y + p.z * cv.z + p.w * cv.w;
            ((float4*)(pi + ((size_t)batch * NN + r0 + r) * NN))[tid] = p;
        }
#pragma unroll
        for (int o = 16; o; o >>= 1)
            cacc += __shfl_xor_sync(0xffffffffu, cacc, o);
        if (lane == 0) wsum[warp][0] = cacc;
        __syncthreads();
        if (tid == 0) {
            float s = 0.f;
#pragma unroll
            for (int w = 0; w < 8; w++) s += wsum[w][0];
            atomicAdd(&cost[batch], s);
        }
        __syncthreads();   // protect smem reuse in the next round
    }
}

// ---------------------------------------------------------------------------
extern "C" void kernel_launch(void* const* d_in, const int* in_sizes, int n_in,
                              void* d_out, int out_size) {
    const float* mu = (const float*)d_in[0];
    const float* nu = (const float*)d_in[1];
    const float* C  = (const float*)d_in[2];
    float* cost = (float*)d_out;                 // outputs: (cost[64], pi[64M])
    float* pi   = (float*)d_out + BATCH;

    // Co-residency-safe grid size (pure queries; deterministic per machine).
    int occ = 0, sms = 0, dev = 0;
    cudaGetDevice(&dev);
    cudaOccupancyMaxActiveBlocksPerMultiprocessor(&occ, sinkhorn_resident, 256, 0);
    cudaDeviceGetAttribute(&sms, cudaDevAttrMultiProcessorCount, dev);
    int teams = (occ * sms) / BPB;
    if (teams > BATCH) teams = BATCH;
    if (teams < 1) teams = 1;

    k_init<<<64, 256>>>(cost);
    sinkhorn_resident<<<teams * BPB, 256>>>(mu, nu, C, cost, pi, teams);
}